// round 2
// baseline (speedup 1.0000x reference)
#include <cuda_runtime.h>

#define BB 256
#define TT 512
#define EMBD 64
#define HID 128

typedef unsigned long long u64t;

__device__ float g_pre1[(long)TT * BB * HID];   // [t][b][j], 64 MB
__device__ float g_h2[BB * HID];

__device__ __forceinline__ void ffma2(u64t& d, u64t a, u64t b) {
    asm("fma.rn.f32x2 %0, %1, %2, %0;" : "+l"(d) : "l"(a), "l"(b));
}
__device__ __forceinline__ float hsum2(u64t v) {
    unsigned lo, hi;
    asm("mov.b64 {%0,%1}, %2;" : "=r"(lo), "=r"(hi) : "l"(v));
    return __uint_as_float(lo) + __uint_as_float(hi);
}

// ---------------------------------------------------------------------------
// Kernel 1: pre1[t][b][j] = dot(emb[x[b,t]], Wih1[j]) + b_ih1[j] + b_hh1[j]
// ---------------------------------------------------------------------------
__global__ __launch_bounds__(128) void k_pre1(
    const int* __restrict__ x, const float* __restrict__ emb,
    const float* __restrict__ Wih1, const float* __restrict__ bih1,
    const float* __restrict__ bhh1)
{
    __shared__ __align__(16) float shW[HID * 68];
    __shared__ __align__(16) float4 shE[8 * 16];
    __shared__ int shX[8];

    const int tid = threadIdx.x;   // output feature j

    for (int it = 0; it < 64; ++it) {
        int f = it * 128 + tid;
        int j = f >> 6, k = f & 63;
        shW[j * 68 + k] = Wih1[f];
    }
    __syncthreads();

    u64t Wr2[32];
    {
        const float* wrow = &shW[tid * 68];
#pragma unroll
        for (int i = 0; i < 32; ++i) {
            unsigned lo = __float_as_uint(wrow[2 * i]);
            unsigned hi = __float_as_uint(wrow[2 * i + 1]);
            asm("mov.b64 %0, {%1,%2};" : "=l"(Wr2[i]) : "r"(lo), "r"(hi));
        }
    }
    const float bb = bih1[tid] + bhh1[tid];

    const int base = blockIdx.x * 256;              // 256 (b,t) rows per block
    const float4* __restrict__ e4 = (const float4*)emb;
    const ulonglong2* shE2 = (const ulonglong2*)shE;

    for (int it = 0; it < 32; ++it) {
        const int rid0 = base + it * 8;             // rid = t*256 + b
        if (tid < 8) {
            int rid = rid0 + tid;
            int t = rid >> 8, b = rid & 255;
            shX[tid] = x[b * TT + t];
        }
        __syncthreads();
        {
            int r = tid >> 4, f = tid & 15;
            shE[r * 16 + f] = e4[(long)shX[r] * 16 + f];
        }
        __syncthreads();

        u64t acc2[8];
#pragma unroll
        for (int r = 0; r < 8; ++r) acc2[r] = 0ull;
#pragma unroll
        for (int k4 = 0; k4 < 16; ++k4) {
#pragma unroll
            for (int r = 0; r < 8; ++r) {
                ulonglong2 e = shE2[r * 16 + k4];
                ffma2(acc2[r], Wr2[2 * k4 + 0], e.x);
                ffma2(acc2[r], Wr2[2 * k4 + 1], e.y);
            }
        }
#pragma unroll
        for (int r = 0; r < 8; ++r)
            g_pre1[(long)(rid0 + r) * HID + tid] = hsum2(acc2[r]) + bb;
        __syncthreads();
    }
}

// ---------------------------------------------------------------------------
// Kernel 2: fused two-layer scan with packed f32x2 FMAs.
// 128 blocks x 256 threads; block handles rows b0,b0+1.
// Thread (j = tid&127, p = tid>>7) holds k-half rows of W_hh1/W_ih2/W_hh2
// as 32 packed f32x2 regs each.
// ---------------------------------------------------------------------------
__global__ __launch_bounds__(256, 1) void k_scan(
    const float* __restrict__ Whh1, const float* __restrict__ Wih2,
    const float* __restrict__ Whh2, const float* __restrict__ bih2,
    const float* __restrict__ bhh2)
{
    __shared__ __align__(16) float sh_h1[2][HID];
    __shared__ __align__(16) float sh_h2[2][HID];
    __shared__ __align__(16) float sh_p[2][2][HID];   // [half][row][j]

    const int tid = threadIdx.x;
    const int j = tid & 127;
    const int p = tid >> 7;            // k-half (uniform per warp)
    const int b0 = blockIdx.x * 2;

    u64t W1r2[32], Wi2r2[32], W2r2[32];
    {
        const ulonglong2* w1 = (const ulonglong2*)(Whh1 + j * HID + p * 64);
        const ulonglong2* wi = (const ulonglong2*)(Wih2 + j * HID + p * 64);
        const ulonglong2* w2 = (const ulonglong2*)(Whh2 + j * HID + p * 64);
#pragma unroll
        for (int i = 0; i < 16; ++i) {
            ulonglong2 a = w1[i]; W1r2[2 * i] = a.x; W1r2[2 * i + 1] = a.y;
            ulonglong2 b = wi[i]; Wi2r2[2 * i] = b.x; Wi2r2[2 * i + 1] = b.y;
            ulonglong2 c = w2[i]; W2r2[2 * i] = c.x; W2r2[2 * i + 1] = c.y;
        }
    }
    const float bb2 = bih2[j] + bhh2[j];

    sh_h1[p][j] = 0.f;
    sh_h2[p][j] = 0.f;
    __syncthreads();

    const float* preBase = g_pre1 + (long)(b0 + p) * HID + j;
    float pre_r = preBase[0];

    const ulonglong2* h0p = (const ulonglong2*)&sh_h1[0][p * 64];
    const ulonglong2* h1p = (const ulonglong2*)&sh_h1[1][p * 64];
    const ulonglong2* g0p = (const ulonglong2*)&sh_h2[0][p * 64];
    const ulonglong2* g1p = (const ulonglong2*)&sh_h2[1][p * 64];

    for (int t = 0; t < TT; ++t) {
        // ---- Phase A: partials of W_hh1 * h1 for both rows ----
        u64t a0 = 0ull, a1 = 0ull;
#pragma unroll
        for (int i = 0; i < 16; ++i) {
            ulonglong2 h0 = h0p[i];
            ffma2(a0, W1r2[2 * i + 0], h0.x);
            ffma2(a0, W1r2[2 * i + 1], h0.y);
            ulonglong2 h1 = h1p[i];
            ffma2(a1, W1r2[2 * i + 0], h1.x);
            ffma2(a1, W1r2[2 * i + 1], h1.y);
        }
        sh_p[p][0][j] = hsum2(a0);
        sh_p[p][1][j] = hsum2(a1);
        __syncthreads();

        // ---- Phase B: combine + tanh; thread (j,p) combines row p ----
        {
            float v = pre_r + sh_p[0][p][j] + sh_p[1][p][j];
            sh_h1[p][j] = tanhf(v);
        }
        if (t + 1 < TT) pre_r = preBase[(long)(t + 1) * BB * HID];
        __syncthreads();

        // ---- Phase C: partials of W_ih2*h1new + W_hh2*h2 for both rows ----
        u64t c0 = 0ull, c1 = 0ull, d0 = 0ull, d1 = 0ull;
#pragma unroll
        for (int i = 0; i < 16; ++i) {
            ulonglong2 h0 = h0p[i];
            ffma2(c0, Wi2r2[2 * i + 0], h0.x);
            ffma2(c0, Wi2r2[2 * i + 1], h0.y);
            ulonglong2 h1 = h1p[i];
            ffma2(c1, Wi2r2[2 * i + 0], h1.x);
            ffma2(c1, Wi2r2[2 * i + 1], h1.y);
            ulonglong2 g0 = g0p[i];
            ffma2(d0, W2r2[2 * i + 0], g0.x);
            ffma2(d0, W2r2[2 * i + 1], g0.y);
            ulonglong2 g1 = g1p[i];
            ffma2(d1, W2r2[2 * i + 0], g1.x);
            ffma2(d1, W2r2[2 * i + 1], g1.y);
        }
        sh_p[p][0][j] = hsum2(c0) + hsum2(d0);
        sh_p[p][1][j] = hsum2(c1) + hsum2(d1);
        __syncthreads();

        // ---- Phase D: combine + tanh for h2 ----
        {
            float v2 = bb2 + sh_p[0][p][j] + sh_p[1][p][j];
            sh_h2[p][j] = tanhf(v2);
        }
        __syncthreads();
    }

    g_h2[(b0 + p) * HID + j] = sh_h2[p][j];
}

// ---------------------------------------------------------------------------
// Kernel 3: epilogue — LN -> proj -> tanh -> LN. One block per batch row.
// ---------------------------------------------------------------------------
__global__ __launch_bounds__(128) void k_epi(
    const float* __restrict__ ln_g, const float* __restrict__ ln_b,
    const float* __restrict__ projW, const float* __restrict__ proj_b,
    const float* __restrict__ on_g, const float* __restrict__ on_b,
    float* __restrict__ out)
{
    __shared__ __align__(16) float sh_rep[HID];
    __shared__ float sh_red[8];

    const int j = threadIdx.x;
    const int b = blockIdx.x;

    float v = g_h2[b * HID + j];

    // LN 1
    float s = v, q = v * v;
#pragma unroll
    for (int o = 16; o; o >>= 1) {
        s += __shfl_xor_sync(0xffffffffu, s, o);
        q += __shfl_xor_sync(0xffffffffu, q, o);
    }
    if ((j & 31) == 0) { sh_red[j >> 5] = s; sh_red[4 + (j >> 5)] = q; }
    __syncthreads();
    s = sh_red[0] + sh_red[1] + sh_red[2] + sh_red[3];
    q = sh_red[4] + sh_red[5] + sh_red[6] + sh_red[7];
    float mu = s * (1.f / HID);
    float var = q * (1.f / HID) - mu * mu;
    float rep = (v - mu) * rsqrtf(var + 1e-5f) * ln_g[j] + ln_b[j];
    sh_rep[j] = rep;
    __syncthreads();

    // proj + tanh
    float acc = proj_b[j];
    const float4* w4 = (const float4*)(projW + j * HID);
    const float4* r4 = (const float4*)sh_rep;
#pragma unroll
    for (int i = 0; i < 32; ++i) {
        float4 w = __ldg(&w4[i]);
        float4 r = r4[i];
        acc = fmaf(w.x, r.x, acc);
        acc = fmaf(w.y, r.y, acc);
        acc = fmaf(w.z, r.z, acc);
        acc = fmaf(w.w, r.w, acc);
    }
    float tv = tanhf(acc);

    // LN 2
    __syncthreads();
    s = tv; q = tv * tv;
#pragma unroll
    for (int o = 16; o; o >>= 1) {
        s += __shfl_xor_sync(0xffffffffu, s, o);
        q += __shfl_xor_sync(0xffffffffu, q, o);
    }
    if ((j & 31) == 0) { sh_red[j >> 5] = s; sh_red[4 + (j >> 5)] = q; }
    __syncthreads();
    s = sh_red[0] + sh_red[1] + sh_red[2] + sh_red[3];
    q = sh_red[4] + sh_red[5] + sh_red[6] + sh_red[7];
    float mu2 = s * (1.f / HID);
    float var2 = q * (1.f / HID) - mu2 * mu2;
    out[b * HID + j] = (tv - mu2) * rsqrtf(var2 + 1e-5f) * on_g[j] + on_b[j];
}

// ---------------------------------------------------------------------------
extern "C" void kernel_launch(void* const* d_in, const int* in_sizes, int n_in,
                              void* d_out, int out_size)
{
    const int*   x     = (const int*)  d_in[0];
    const float* emb   = (const float*)d_in[1];
    const float* Wih1  = (const float*)d_in[2];
    const float* bih1  = (const float*)d_in[3];
    const float* Whh1  = (const float*)d_in[4];
    const float* bhh1  = (const float*)d_in[5];
    const float* Wih2  = (const float*)d_in[6];
    const float* bih2  = (const float*)d_in[7];
    const float* Whh2  = (const float*)d_in[8];
    const float* bhh2  = (const float*)d_in[9];
    const float* ln_g  = (const float*)d_in[10];
    const float* ln_b  = (const float*)d_in[11];
    const float* projW = (const float*)d_in[12];
    const float* projb = (const float*)d_in[13];
    const float* on_g  = (const float*)d_in[14];
    const float* on_b  = (const float*)d_in[15];

    k_pre1<<<512, 128>>>(x, emb, Wih1, bih1, bhh1);
    k_scan<<<128, 256>>>(Whh1, Wih2, Whh2, bih2, bhh2);
    k_epi<<<256, 128>>>(ln_g, ln_b, projW, projb, on_g, on_b, (float*)d_out);
}